// round 16
// baseline (speedup 1.0000x reference)
#include <cuda_runtime.h>
#include <cuda_fp16.h>
#include <cstdint>

#define USER_NUM 200000
#define ITEM_NUM 100000
#define N_NODES  (USER_NUM + ITEM_NUM)   // 300000
#define EMB      64
#define N_EDGES  4800000

#define SCAN_N        (N_NODES + 1)
#define SCAN_PER_TH   8
#define SCAN_BLK      1024
#define SCAN_TILE     (SCAN_BLK * SCAN_PER_TH)                  // 8192
#define SCAN_NBLK     ((SCAN_N + SCAN_TILE - 1) / SCAN_TILE)    // 37

// ---------------- static device scratch (no allocation allowed) ----------------
__device__ int     g_deg[SCAN_N];
__device__ int     g_row_ptr[SCAN_N];
__device__ int     g_cursor[N_NODES];
__device__ int     g_part[SCAN_NBLK];
__device__ int2    g_edges[N_EDGES];                    // sorted-by-src (dst, val-bits)
__device__ __half2 g_x0[(size_t)N_NODES * EMB / 2];     // fp16 input features
__device__ __half2 g_h1[(size_t)N_NODES * EMB / 2];     // layer-1 output (fp16)
__device__ __half2 g_h2[(size_t)N_NODES * EMB / 2];     // layer-2 output (fp16)

// ---------------- build kernels (R14 plateau form) ----------------
__global__ void zero_deg_kernel() {
    for (int i = blockIdx.x * blockDim.x + threadIdx.x; i < SCAN_N; i += gridDim.x * blockDim.x)
        g_deg[i] = 0;
}

__global__ void hist_kernel(const int4* __restrict__ src4) {
    const int n4 = N_EDGES / 4;
    for (int e = blockIdx.x * blockDim.x + threadIdx.x; e < n4; e += gridDim.x * blockDim.x) {
        int4 s = __ldcs(&src4[e]);
        atomicAdd(&g_deg[s.x], 1);
        atomicAdd(&g_deg[s.y], 1);
        atomicAdd(&g_deg[s.z], 1);
        atomicAdd(&g_deg[s.w], 1);
    }
}

__device__ __forceinline__ int warp_incl_scan(int v, int lane) {
#pragma unroll
    for (int off = 1; off < 32; off <<= 1) {
        int y = __shfl_up_sync(0xffffffffu, v, off);
        if (lane >= off) v += y;
    }
    return v;
}

__global__ void __launch_bounds__(SCAN_BLK) scanA_kernel() {
    __shared__ int warp_sums[32];
    int idx0 = blockIdx.x * SCAN_TILE + threadIdx.x * SCAN_PER_TH;
    int local = 0;
#pragma unroll
    for (int i = 0; i < SCAN_PER_TH; i++) {
        int idx = idx0 + i;
        local += (idx < SCAN_N) ? g_deg[idx] : 0;
    }
    int lane = threadIdx.x & 31, wid = threadIdx.x >> 5;
    int incl = warp_incl_scan(local, lane);
    if (lane == 31) warp_sums[wid] = incl;
    __syncthreads();
    if (wid == 0) {
        int w = (lane < 32) ? warp_sums[lane] : 0;
        w = warp_incl_scan(w, lane);
        if (lane == 31) g_part[blockIdx.x] = w;
    }
}

__global__ void scanB_kernel() {
    int lane = threadIdx.x;   // 64 threads, SCAN_NBLK <= 64
    int v = (lane < SCAN_NBLK) ? g_part[lane] : 0;
    int l5 = lane & 31, w = lane >> 5;
    __shared__ int ws[2];
    int incl = warp_incl_scan(v, l5);
    if (l5 == 31) ws[w] = incl;
    __syncthreads();
    int excl = incl - v + (w ? ws[0] : 0);
    if (lane < SCAN_NBLK) g_part[lane] = excl;
}

__global__ void __launch_bounds__(SCAN_BLK) scanC_kernel() {
    __shared__ int warp_sums[32];
    int idx0 = blockIdx.x * SCAN_TILE + threadIdx.x * SCAN_PER_TH;
    int vals[SCAN_PER_TH];
    int local = 0;
#pragma unroll
    for (int i = 0; i < SCAN_PER_TH; i++) {
        int idx = idx0 + i;
        int v = (idx < SCAN_N) ? g_deg[idx] : 0;
        vals[i] = local;
        local += v;
    }
    int lane = threadIdx.x & 31, wid = threadIdx.x >> 5;
    int incl = warp_incl_scan(local, lane);
    if (lane == 31) warp_sums[wid] = incl;
    __syncthreads();
    if (wid == 0) {
        int w = warp_sums[lane];
        warp_sums[lane] = warp_incl_scan(w, lane);
    }
    __syncthreads();
    int excl = incl - local + (wid > 0 ? warp_sums[wid - 1] : 0) + g_part[blockIdx.x];
#pragma unroll
    for (int i = 0; i < SCAN_PER_TH; i++) {
        int idx = idx0 + i;
        if (idx < SCAN_N) {
            int r = excl + vals[i];
            g_row_ptr[idx] = r;
            if (idx < N_NODES) g_cursor[idx] = r;
        }
    }
}

__global__ void scatter_kernel(const int* __restrict__ src,
                               const int* __restrict__ dst,
                               const float* __restrict__ val) {
    for (int e = blockIdx.x * blockDim.x + threadIdx.x; e < N_EDGES; e += gridDim.x * blockDim.x) {
        int s = __ldcs(&src[e]);
        int p = atomicAdd(&g_cursor[s], 1);
        int2 ev = make_int2(__ldcs(&dst[e]), __float_as_int(__ldcs(&val[e])));
        __stcs(&g_edges[p], ev);
    }
}

// fp32 user/item -> fp16 g_x0 (concatenated)
__global__ void convert_kernel(const float2* __restrict__ u, const float2* __restrict__ it) {
    const int nU = USER_NUM * EMB / 2;
    const int nT = N_NODES * EMB / 2;
    for (int i = blockIdx.x * blockDim.x + threadIdx.x; i < nT; i += gridDim.x * blockDim.x) {
        float2 v = (i < nU) ? __ldcs(&u[i]) : __ldcs(&it[i - nU]);
        __stcs(&g_x0[i], __floats2half2_rn(v.x, v.y));
    }
}

// ---------------- SpMM: one warp/row, paired int4 edge loads, unroll 8 ----------
// ncu R15: DRAM 10.8%, L2 24.4%, issue 45.6% -> issue/latency-bound, not memory.
// Deeper unroll = more independent edge+gather loads in flight per warp.
// mode 0: x = g_x0 -> g_h1 ; mode 1: x = g_h1 -> g_h2
// mode 2: x = g_h2 -> out = (h1 + h2 + s)/3
__global__ void __launch_bounds__(256) spmm_kernel(float* __restrict__ out, int mode) {
    int gw = (blockIdx.x * blockDim.x + threadIdx.x) >> 5;
    if (gw >= N_NODES) return;
    unsigned lane = threadIdx.x & 31;

    const __half2* __restrict__ x =
        (mode == 0) ? g_x0 : (mode == 1) ? g_h1 : g_h2;

    int beg = __ldg(&g_row_ptr[gw]);
    int end = __ldg(&g_row_ptr[gw + 1]);

    float sx = 0.f, sy = 0.f;
    int j = beg;

    // peel to even index for 16B-aligned int4 edge loads
    if (j < end && (j & 1)) {
        int2 e = __ldcs(&g_edges[j]);
        float2 xv = __half22float2(__ldg(x + (((unsigned)e.x << 5) + lane)));
        float vv = __int_as_float(e.y);
        sx = fmaf(vv, xv.x, sx);
        sy = fmaf(vv, xv.y, sy);
        j++;
    }
#pragma unroll 8
    for (; j + 1 < end; j += 2) {
        int4 e2 = __ldcs(reinterpret_cast<const int4*>(&g_edges[j]));   // 2 edges
        unsigned o0 = ((unsigned)e2.x << 5) + lane;
        unsigned o1 = ((unsigned)e2.z << 5) + lane;
        float2 x0 = __half22float2(__ldg(x + o0));
        float2 x1 = __half22float2(__ldg(x + o1));
        float v0 = __int_as_float(e2.y);
        float v1 = __int_as_float(e2.w);
        sx = fmaf(v0, x0.x, sx);
        sy = fmaf(v0, x0.y, sy);
        sx = fmaf(v1, x1.x, sx);
        sy = fmaf(v1, x1.y, sy);
    }
    if (j < end) {
        int2 e = __ldcs(&g_edges[j]);
        float2 xv = __half22float2(__ldg(x + (((unsigned)e.x << 5) + lane)));
        float vv = __int_as_float(e.y);
        sx = fmaf(vv, xv.x, sx);
        sy = fmaf(vv, xv.y, sy);
    }

    unsigned off32 = ((unsigned)gw << 5) + lane;
    if (mode == 0) {
        __stcs(&g_h1[off32], __floats2half2_rn(sx, sy));
    } else if (mode == 1) {
        __stcs(&g_h2[off32], __floats2half2_rn(sx, sy));
    } else {
        const float inv3 = 1.0f / 3.0f;
        float2 b1 = __half22float2(__ldcs(&g_h1[off32]));
        float2 b2 = __half22float2(__ldcs(&g_h2[off32]));
        float2 r;
        r.x = (b1.x + b2.x + sx) * inv3;
        r.y = (b1.y + b2.y + sy) * inv3;
        *reinterpret_cast<float2*>(out + (((unsigned)gw << 6) + (lane << 1))) = r;
    }
}

// ---------------- launch ----------------
extern "C" void kernel_launch(void* const* d_in, const int* in_sizes, int n_in,
                              void* d_out, int out_size) {
    const float* user_emb = (const float*)d_in[0];
    const float* item_emb = (const float*)d_in[1];
    const float* edge_val = (const float*)d_in[2];
    const int*   edge_src = (const int*)d_in[3];
    const int*   edge_dst = (const int*)d_in[4];
    float* out = (float*)d_out;

    const int TB = 256;
    const int edge_grid  = (N_EDGES + TB - 1) / TB;
    const int edge4_grid = (N_EDGES / 4 + TB - 1) / TB;
    const int node_grid  = (SCAN_N + TB - 1) / TB;
    const int spmm_grid  = (N_NODES * 32 + TB - 1) / TB;   // 8 warps/block
    const int conv_grid  = (N_NODES * EMB / 2 + TB - 1) / TB;

    zero_deg_kernel<<<node_grid, TB>>>();
    hist_kernel<<<edge4_grid, TB>>>((const int4*)edge_src);
    scanA_kernel<<<SCAN_NBLK, SCAN_BLK>>>();
    scanB_kernel<<<1, 64>>>();
    scanC_kernel<<<SCAN_NBLK, SCAN_BLK>>>();
    scatter_kernel<<<edge_grid, TB>>>(edge_src, edge_dst, edge_val);
    convert_kernel<<<conv_grid, TB>>>((const float2*)user_emb, (const float2*)item_emb);

    spmm_kernel<<<spmm_grid, TB>>>(out, 0);   // L1 -> h1
    spmm_kernel<<<spmm_grid, TB>>>(out, 1);   // L2 -> h2
    spmm_kernel<<<spmm_grid, TB>>>(out, 2);   // L3 + combine -> out
}

// round 17
// speedup vs baseline: 1.1195x; 1.1195x over previous
#include <cuda_runtime.h>
#include <cuda_fp16.h>
#include <cstdint>

#define USER_NUM 200000
#define ITEM_NUM 100000
#define N_NODES  (USER_NUM + ITEM_NUM)   // 300000
#define EMB      64
#define N_EDGES  4800000

#define SCAN_N        (N_NODES + 1)
#define SCAN_PER_TH   8
#define SCAN_BLK      1024
#define SCAN_TILE     (SCAN_BLK * SCAN_PER_TH)                  // 8192
#define SCAN_NBLK     ((SCAN_N + SCAN_TILE - 1) / SCAN_TILE)    // 37

// ---------------- static device scratch (no allocation allowed) ----------------
__device__ int     g_deg[SCAN_N];
__device__ int     g_row_ptr[SCAN_N];
__device__ int     g_cursor[N_NODES];
__device__ int     g_part[SCAN_NBLK];
__device__ int2    g_edges[N_EDGES];                    // sorted-by-src (dst, val-bits)
__device__ __half2 g_x0[(size_t)N_NODES * EMB / 2];     // fp16 input features
__device__ __half2 g_h1[(size_t)N_NODES * EMB / 2];     // layer-1 output (fp16)
__device__ __half2 g_h2[(size_t)N_NODES * EMB / 2];     // layer-2 output (fp16)

// ---------------- build kernels (R14 plateau form) ----------------
__global__ void zero_deg_kernel() {
    for (int i = blockIdx.x * blockDim.x + threadIdx.x; i < SCAN_N; i += gridDim.x * blockDim.x)
        g_deg[i] = 0;
}

__global__ void hist_kernel(const int4* __restrict__ src4) {
    const int n4 = N_EDGES / 4;
    for (int e = blockIdx.x * blockDim.x + threadIdx.x; e < n4; e += gridDim.x * blockDim.x) {
        int4 s = __ldcs(&src4[e]);
        atomicAdd(&g_deg[s.x], 1);
        atomicAdd(&g_deg[s.y], 1);
        atomicAdd(&g_deg[s.z], 1);
        atomicAdd(&g_deg[s.w], 1);
    }
}

__device__ __forceinline__ int warp_incl_scan(int v, int lane) {
#pragma unroll
    for (int off = 1; off < 32; off <<= 1) {
        int y = __shfl_up_sync(0xffffffffu, v, off);
        if (lane >= off) v += y;
    }
    return v;
}

__global__ void __launch_bounds__(SCAN_BLK) scanA_kernel() {
    __shared__ int warp_sums[32];
    int idx0 = blockIdx.x * SCAN_TILE + threadIdx.x * SCAN_PER_TH;
    int local = 0;
#pragma unroll
    for (int i = 0; i < SCAN_PER_TH; i++) {
        int idx = idx0 + i;
        local += (idx < SCAN_N) ? g_deg[idx] : 0;
    }
    int lane = threadIdx.x & 31, wid = threadIdx.x >> 5;
    int incl = warp_incl_scan(local, lane);
    if (lane == 31) warp_sums[wid] = incl;
    __syncthreads();
    if (wid == 0) {
        int w = (lane < 32) ? warp_sums[lane] : 0;
        w = warp_incl_scan(w, lane);
        if (lane == 31) g_part[blockIdx.x] = w;
    }
}

__global__ void scanB_kernel() {
    int lane = threadIdx.x;   // 64 threads, SCAN_NBLK <= 64
    int v = (lane < SCAN_NBLK) ? g_part[lane] : 0;
    int l5 = lane & 31, w = lane >> 5;
    __shared__ int ws[2];
    int incl = warp_incl_scan(v, l5);
    if (l5 == 31) ws[w] = incl;
    __syncthreads();
    int excl = incl - v + (w ? ws[0] : 0);
    if (lane < SCAN_NBLK) g_part[lane] = excl;
}

__global__ void __launch_bounds__(SCAN_BLK) scanC_kernel() {
    __shared__ int warp_sums[32];
    int idx0 = blockIdx.x * SCAN_TILE + threadIdx.x * SCAN_PER_TH;
    int vals[SCAN_PER_TH];
    int local = 0;
#pragma unroll
    for (int i = 0; i < SCAN_PER_TH; i++) {
        int idx = idx0 + i;
        int v = (idx < SCAN_N) ? g_deg[idx] : 0;
        vals[i] = local;
        local += v;
    }
    int lane = threadIdx.x & 31, wid = threadIdx.x >> 5;
    int incl = warp_incl_scan(local, lane);
    if (lane == 31) warp_sums[wid] = incl;
    __syncthreads();
    if (wid == 0) {
        int w = warp_sums[lane];
        warp_sums[lane] = warp_incl_scan(w, lane);
    }
    __syncthreads();
    int excl = incl - local + (wid > 0 ? warp_sums[wid - 1] : 0) + g_part[blockIdx.x];
#pragma unroll
    for (int i = 0; i < SCAN_PER_TH; i++) {
        int idx = idx0 + i;
        if (idx < SCAN_N) {
            int r = excl + vals[i];
            g_row_ptr[idx] = r;
            if (idx < N_NODES) g_cursor[idx] = r;
        }
    }
}

__global__ void scatter_kernel(const int* __restrict__ src,
                               const int* __restrict__ dst,
                               const float* __restrict__ val) {
    for (int e = blockIdx.x * blockDim.x + threadIdx.x; e < N_EDGES; e += gridDim.x * blockDim.x) {
        int s = __ldcs(&src[e]);
        int p = atomicAdd(&g_cursor[s], 1);
        int2 ev = make_int2(__ldcs(&dst[e]), __float_as_int(__ldcs(&val[e])));
        __stcs(&g_edges[p], ev);
    }
}

// fp32 user/item -> fp16 g_x0 (concatenated)
__global__ void convert_kernel(const float2* __restrict__ u, const float2* __restrict__ it) {
    const int nU = USER_NUM * EMB / 2;
    const int nT = N_NODES * EMB / 2;
    for (int i = blockIdx.x * blockDim.x + threadIdx.x; i < nT; i += gridDim.x * blockDim.x) {
        float2 v = (i < nU) ? __ldcs(&u[i]) : __ldcs(&it[i - nU]);
        __stcs(&g_x0[i], __floats2half2_rn(v.x, v.y));
    }
}

// ---------------- SpMM: one warp/row, paired int4 edge loads, unroll 4 ----------
// Edge loads are L1-cached (__ldg): one 128B line serves 8 consecutive int4
// loads of the same warp — evict-first (__ldcs) was forcing the dependency
// chain's head to L2 latency each iteration (ncu R15: issue 45.6%, no pipe hot).
// mode 0: x = g_x0 -> g_h1 ; mode 1: x = g_h1 -> g_h2
// mode 2: x = g_h2 -> out = (h1 + h2 + s)/3
__global__ void __launch_bounds__(256) spmm_kernel(float* __restrict__ out, int mode) {
    int gw = (blockIdx.x * blockDim.x + threadIdx.x) >> 5;
    if (gw >= N_NODES) return;
    unsigned lane = threadIdx.x & 31;

    const __half2* __restrict__ x =
        (mode == 0) ? g_x0 : (mode == 1) ? g_h1 : g_h2;

    int beg = __ldg(&g_row_ptr[gw]);
    int end = __ldg(&g_row_ptr[gw + 1]);

    float sx = 0.f, sy = 0.f;
    int j = beg;

    // peel to even index for 16B-aligned int4 edge loads
    if (j < end && (j & 1)) {
        int2 e = __ldg(&g_edges[j]);
        float2 xv = __half22float2(__ldg(x + (((unsigned)e.x << 5) + lane)));
        float vv = __int_as_float(e.y);
        sx = fmaf(vv, xv.x, sx);
        sy = fmaf(vv, xv.y, sy);
        j++;
    }
#pragma unroll 4
    for (; j + 1 < end; j += 2) {
        int4 e2 = __ldg(reinterpret_cast<const int4*>(&g_edges[j]));   // 2 edges, L1-cached
        unsigned o0 = ((unsigned)e2.x << 5) + lane;
        unsigned o1 = ((unsigned)e2.z << 5) + lane;
        float2 x0 = __half22float2(__ldg(x + o0));
        float2 x1 = __half22float2(__ldg(x + o1));
        float v0 = __int_as_float(e2.y);
        float v1 = __int_as_float(e2.w);
        sx = fmaf(v0, x0.x, sx);
        sy = fmaf(v0, x0.y, sy);
        sx = fmaf(v1, x1.x, sx);
        sy = fmaf(v1, x1.y, sy);
    }
    if (j < end) {
        int2 e = __ldg(&g_edges[j]);
        float2 xv = __half22float2(__ldg(x + (((unsigned)e.x << 5) + lane)));
        float vv = __int_as_float(e.y);
        sx = fmaf(vv, xv.x, sx);
        sy = fmaf(vv, xv.y, sy);
    }

    unsigned off32 = ((unsigned)gw << 5) + lane;
    if (mode == 0) {
        __stcs(&g_h1[off32], __floats2half2_rn(sx, sy));
    } else if (mode == 1) {
        __stcs(&g_h2[off32], __floats2half2_rn(sx, sy));
    } else {
        const float inv3 = 1.0f / 3.0f;
        float2 b1 = __half22float2(__ldcs(&g_h1[off32]));
        float2 b2 = __half22float2(__ldcs(&g_h2[off32]));
        float2 r;
        r.x = (b1.x + b2.x + sx) * inv3;
        r.y = (b1.y + b2.y + sy) * inv3;
        *reinterpret_cast<float2*>(out + (((unsigned)gw << 6) + (lane << 1))) = r;
    }
}

// ---------------- launch ----------------
extern "C" void kernel_launch(void* const* d_in, const int* in_sizes, int n_in,
                              void* d_out, int out_size) {
    const float* user_emb = (const float*)d_in[0];
    const float* item_emb = (const float*)d_in[1];
    const float* edge_val = (const float*)d_in[2];
    const int*   edge_src = (const int*)d_in[3];
    const int*   edge_dst = (const int*)d_in[4];
    float* out = (float*)d_out;

    const int TB = 256;
    const int edge_grid  = (N_EDGES + TB - 1) / TB;
    const int edge4_grid = (N_EDGES / 4 + TB - 1) / TB;
    const int node_grid  = (SCAN_N + TB - 1) / TB;
    const int spmm_grid  = (N_NODES * 32 + TB - 1) / TB;   // 8 warps/block
    const int conv_grid  = (N_NODES * EMB / 2 + TB - 1) / TB;

    zero_deg_kernel<<<node_grid, TB>>>();
    hist_kernel<<<edge4_grid, TB>>>((const int4*)edge_src);
    scanA_kernel<<<SCAN_NBLK, SCAN_BLK>>>();
    scanB_kernel<<<1, 64>>>();
    scanC_kernel<<<SCAN_NBLK, SCAN_BLK>>>();
    scatter_kernel<<<edge_grid, TB>>>(edge_src, edge_dst, edge_val);
    convert_kernel<<<conv_grid, TB>>>((const float2*)user_emb, (const float2*)item_emb);

    spmm_kernel<<<spmm_grid, TB>>>(out, 0);   // L1 -> h1
    spmm_kernel<<<spmm_grid, TB>>>(out, 1);   // L2 -> h2
    spmm_kernel<<<spmm_grid, TB>>>(out, 2);   // L3 + combine -> out
}